// round 15
// baseline (speedup 1.0000x reference)
#include <cuda_runtime.h>
#include <cuda_fp16.h>
#include <math.h>

#define BDIM 32
#define CDIM 256
#define TDIM 64
#define VDIM 50
#define TOK (BDIM*TDIM*VDIM)   // 102400
#define TV  (TDIM*VDIM)        // 3200
#define C2  512
#define C4  1024

// ---------------- scratch ----------------
__device__ float  g_out1[TOK*CDIM];   // proj + skip (fp32)
__device__ __half h_f   [TOK*C2];     // map output (half)
__device__ __half h_xln [TOK*CDIM];
__device__ __half h_cat [TOK*CDIM];
__device__ __half h_ln2 [TOK*CDIM];
__device__ __half h_h   [TOK*C4];
__device__ __half2 w_map [(CDIM/2)*C2];
__device__ __half2 w_proj[(CDIM/2)*CDIM];
__device__ __half2 w_m1  [(CDIM/2)*C4];
__device__ __half2 w_m2  [(C4/2)*CDIM];

__device__ __forceinline__ unsigned sptr(const void* p) {
    return (unsigned)__cvta_generic_to_shared(p);
}
__device__ __forceinline__ void cpa16(unsigned d, const void* s) {
    asm volatile("cp.async.cg.shared.global [%0], [%1], 16;\n" :: "r"(d), "l"(s));
}

// ---------------- merged weight convert ----------------
__device__ __forceinline__ void wpair1(const float* __restrict__ w,
                                       __half2* __restrict__ o, int idx, int N) {
    int k2 = idx / N, n = idx - k2*N;
    o[idx] = __floats2half2_rn(w[(size_t)(2*k2)*N + n], w[(size_t)(2*k2+1)*N + n]);
}
#define WS1 65536
#define WS2 32768
#define WS3 131072
#define WS4 131072
__global__ __launch_bounds__(256) void k_wall(const float* __restrict__ w1, __half2* o1,
                                              const float* __restrict__ w2, __half2* o2,
                                              const float* __restrict__ w3, __half2* o3,
                                              const float* __restrict__ w4, __half2* o4) {
    int idx = blockIdx.x*256 + threadIdx.x;
    if (idx < WS1) { wpair1(w1, o1, idx, C2); return; }
    idx -= WS1;
    if (idx < WS2) { wpair1(w2, o2, idx, CDIM); return; }
    idx -= WS2;
    if (idx < WS3) { wpair1(w3, o3, idx, C4); return; }
    idx -= WS3;
    if (idx < WS4) { wpair1(w4, o4, idx, CDIM); return; }
}

// ---------------- fused transpose + LN1 (h_xln only) ----------------
__global__ __launch_bounds__(256) void k_transln(const float* __restrict__ x,
                                                 const float* __restrict__ w,
                                                 const float* __restrict__ b) {
    int bt = blockIdx.x;
    int bb = bt / TDIM, t = bt % TDIM;
    __shared__ float s[CDIM][51];
    int tid = threadIdx.x, lane = tid & 31, warp = tid >> 5;
    const float* xp = x + (size_t)bb*CDIM*TV + (size_t)t*VDIM;
    for (int i = tid; i < CDIM*VDIM; i += 256) {
        int c = i / VDIM, v = i - c*VDIM;
        s[c][v] = xp[(size_t)c*TV + v];
    }
    __syncthreads();
    size_t tok0 = (size_t)bt*VDIM;
    for (int v = warp; v < VDIM; v += 8) {
        float q[8], s1 = 0.f, s2 = 0.f;
        #pragma unroll
        for (int i = 0; i < 8; i++) {
            q[i] = s[lane + 32*i][v];
            s1 += q[i]; s2 += q[i]*q[i];
        }
        #pragma unroll
        for (int o = 16; o; o >>= 1) {
            s1 += __shfl_xor_sync(0xffffffffu, s1, o);
            s2 += __shfl_xor_sync(0xffffffffu, s2, o);
        }
        float mean = s1 * (1.0f/CDIM);
        float var  = s2 * (1.0f/CDIM) - mean*mean;
        float rstd = rsqrtf(var + 1e-5f);
        size_t base = (tok0 + v)*CDIM;
        #pragma unroll
        for (int i = 0; i < 8; i++) {
            int c = lane + 32*i;
            h_xln[base + c] = __float2half((q[i] - mean) * rstd * w[c] + b[c]);
        }
    }
}

// ---------------- LayerNorm: one token per warp ----------------
__global__ __launch_bounds__(256) void k_ln(const float* __restrict__ src,
                                            __half* __restrict__ dst,
                                            const float* __restrict__ w,
                                            const float* __restrict__ b) {
    size_t m = (size_t)blockIdx.x*8 + (threadIdx.x >> 5);
    int lane = threadIdx.x & 31;
    int c0 = lane*8;
    const float* row = src + m*CDIM + c0;
    float q[8];
    *(float4*)(q)   = *(const float4*)(row);
    *(float4*)(q+4) = *(const float4*)(row + 4);
    float s1 = 0.f, s2 = 0.f;
    #pragma unroll
    for (int i = 0; i < 8; i++) { s1 += q[i]; s2 += q[i]*q[i]; }
    #pragma unroll
    for (int o = 16; o; o >>= 1) {
        s1 += __shfl_xor_sync(0xffffffffu, s1, o);
        s2 += __shfl_xor_sync(0xffffffffu, s2, o);
    }
    float mean = s1 * (1.0f/CDIM);
    float var  = s2 * (1.0f/CDIM) - mean*mean;
    float rstd = rsqrtf(var + 1e-5f);
    float4 wv0 = *(const float4*)&w[c0], wv1 = *(const float4*)&w[c0+4];
    float4 bv0 = *(const float4*)&b[c0], bv1 = *(const float4*)&b[c0+4];
    const float wr[8] = {wv0.x,wv0.y,wv0.z,wv0.w,wv1.x,wv1.y,wv1.z,wv1.w};
    const float br[8] = {bv0.x,bv0.y,bv0.z,bv0.w,bv1.x,bv1.y,bv1.z,bv1.w};
    __half2 pk[4];
    #pragma unroll
    for (int i = 0; i < 4; i++) {
        float v0 = (q[2*i]   - mean) * rstd * wr[2*i]   + br[2*i];
        float v1 = (q[2*i+1] - mean) * rstd * wr[2*i+1] + br[2*i+1];
        pk[i] = __floats2half2_rn(v0, v1);
    }
    *(uint4*)(dst + m*CDIM + c0) = *(const uint4*)pk;
}

// ---------------- fp16 tensor-core GEMM 128x128x32, cp.async 3-stage ----------------
// EPI: 2 bias+gelu->half | 3 bias->half
//      4 bias+extra(out1) -> transposed store to (B,C,T,V) fp32 out
//      5 bias + skip read directly from x (B,C,T,V) -> f32 out
#define SA 40
#define SB 136
template<int EPI>
__global__ __launch_bounds__(256, 2) void k_gemm_h(const __half* __restrict__ A,
                                                   const __half2* __restrict__ Bp,
                                                   const float* __restrict__ bias,
                                                   const float* __restrict__ extra,
                                                   void* __restrict__ Cout,
                                                   int M, int N, int K) {
    __shared__ __align__(16) __half  As[3][128*SA];
    __shared__ __align__(16) __half2 Bs[3][16*SB];
    int tid = threadIdx.x, lane = tid & 31, warp = tid >> 5;
    int wm = warp >> 2, wn = warp & 3;
    int m0 = blockIdx.y * 128, n0 = blockIdx.x * 128;
    int r = lane >> 2, c = lane & 3;

    float acc[4][4][4];
    #pragma unroll
    for (int i = 0; i < 4; i++)
        #pragma unroll
        for (int j = 0; j < 4; j++)
            #pragma unroll
            for (int q = 0; q < 4; q++) acc[i][j][q] = 0.f;

    auto stage = [&](int s, int k0) {
        #pragma unroll
        for (int hh = 0; hh < 2; hh++) {
            int ch = tid + hh*256;
            int row = ch >> 2, seg = ch & 3;
            cpa16(sptr(&As[s][row*SA + seg*8]),
                  A + (size_t)(m0+row)*K + k0 + seg*8);
        }
        int k20 = k0 >> 1;
        #pragma unroll
        for (int hh = 0; hh < 2; hh++) {
            int ch = tid + hh*256;
            int k2 = ch >> 5, seg = ch & 31;
            cpa16(sptr(&Bs[s][k2*SB + seg*4]),
                  Bp + (size_t)(k20+k2)*N + n0 + seg*4);
        }
    };

    int nt = K >> 5;
    stage(0, 0);
    asm volatile("cp.async.commit_group;\n");
    stage(1, 32);
    asm volatile("cp.async.commit_group;\n");

    int lrow = (lane & 7) + ((lane >> 3) & 1)*8;
    int lcol = ((lane >> 4) & 1)*8;

    for (int t = 0; t < nt; t++) {
        if (t+1 < nt) asm volatile("cp.async.wait_group 1;\n");
        else          asm volatile("cp.async.wait_group 0;\n");
        __syncthreads();
        int s = t % 3;
        #pragma unroll
        for (int kk = 0; kk < 32; kk += 16) {
            unsigned af[4][4];
            #pragma unroll
            for (int i = 0; i < 4; i++) {
                int row = wm*64 + i*16 + lrow;
                unsigned ad = sptr(&As[s][row*SA + kk + lcol]);
                asm volatile("ldmatrix.sync.aligned.m8n8.x4.shared.b16 {%0,%1,%2,%3}, [%4];"
                    : "=r"(af[i][0]), "=r"(af[i][1]), "=r"(af[i][2]), "=r"(af[i][3])
                    : "r"(ad));
            }
            int kk2 = kk >> 1;
            unsigned bf[4][2];
            #pragma unroll
            for (int j = 0; j < 4; j++) {
                int nb = wn*32 + j*8 + r;
                bf[j][0] = *(const unsigned*)&Bs[s][(kk2+c  )*SB + nb];
                bf[j][1] = *(const unsigned*)&Bs[s][(kk2+c+4)*SB + nb];
            }
            #pragma unroll
            for (int i = 0; i < 4; i++)
                #pragma unroll
                for (int j = 0; j < 4; j++) {
                    asm volatile(
                        "mma.sync.aligned.m16n8k16.row.col.f32.f16.f16.f32 "
                        "{%0,%1,%2,%3}, {%4,%5,%6,%7}, {%8,%9}, {%0,%1,%2,%3};"
                        : "+f"(acc[i][j][0]), "+f"(acc[i][j][1]),
                          "+f"(acc[i][j][2]), "+f"(acc[i][j][3])
                        : "r"(af[i][0]), "r"(af[i][1]), "r"(af[i][2]), "r"(af[i][3]),
                          "r"(bf[j][0]), "r"(bf[j][1]));
                }
        }
        if (t+2 < nt) {
            stage((t+2) % 3, (t+2)*32);
            asm volatile("cp.async.commit_group;\n");
        }
    }

    if (EPI == 4) {
        float* tb = (float*)&As[0][0];
        int bidx = m0 / TV;
        int rem0 = m0 % TV;
        #pragma unroll 1
        for (int wmt = 0; wmt < 2; wmt++) {
            #pragma unroll 1
            for (int i = 0; i < 4; i++) {
                __syncthreads();
                if (wm == wmt) {
                    #pragma unroll
                    for (int j = 0; j < 4; j++) {
                        int colb = wn*32 + j*8 + c*2;
                        float b0 = bias[n0+colb], b1 = bias[n0+colb+1];
                        #pragma unroll
                        for (int hh = 0; hh < 2; hh++) {
                            int rl = r + hh*8;
                            size_t mrow = (size_t)(m0 + wmt*64 + i*16 + rl);
                            const float2 e = *(const float2*)&extra[mrow*N + n0 + colb];
                            tb[colb*20 + rl]     = acc[i][j][2*hh]   + b0 + e.x;
                            tb[(colb+1)*20 + rl] = acc[i][j][2*hh+1] + b1 + e.y;
                        }
                    }
                }
                __syncthreads();
                int col = tid >> 1, rh = tid & 1;
                int cg = n0 + col;
                int rowbase = wmt*64 + i*16 + rh*8;
                float4 o1 = *(float4*)&tb[col*20 + rh*8];
                float4 o2 = *(float4*)&tb[col*20 + rh*8 + 4];
                size_t oaddr = (size_t)bidx*CDIM*TV + (size_t)cg*TV + rem0 + rowbase;
                *(float4*)&((float*)Cout)[oaddr]     = o1;
                *(float4*)&((float*)Cout)[oaddr + 4] = o2;
            }
        }
        return;
    }

    int bq = m0 / TV, rq = m0 % TV;
    #pragma unroll
    for (int i = 0; i < 4; i++) {
        #pragma unroll
        for (int j = 0; j < 4; j++) {
            int row0 = m0 + wm*64 + i*16 + r;
            int col  = n0 + wn*32 + j*8 + c*2;
            float b0 = bias[col], b1 = bias[col+1];
            #pragma unroll
            for (int hh = 0; hh < 2; hh++) {
                size_t mrow = (size_t)(row0 + hh*8);
                float v0 = acc[i][j][2*hh+0] + b0;
                float v1 = acc[i][j][2*hh+1] + b1;
                if (EPI == 5) {
                    int local = wm*64 + i*16 + r + hh*8;
                    size_t xoff = (size_t)(bq*CDIM + col)*TV + rq + local;
                    v0 += extra[xoff];
                    v1 += extra[xoff + TV];
                }
                if (EPI == 2) {
                    v0 = 0.5f * v0 * (1.0f + erff(v0 * 0.70710678118654752f));
                    v1 = 0.5f * v1 * (1.0f + erff(v1 * 0.70710678118654752f));
                }
                if (EPI == 2 || EPI == 3) {
                    *(__half2*)((__half*)Cout + mrow*N + col) = __floats2half2_rn(v0, v1);
                } else {
                    float2 o; o.x = v0; o.y = v1;
                    *(float2*)((float*)Cout + mrow*N + col) = o;
                }
            }
        }
    }
}

// ---------------- merged branches ----------------
#define NB_A (4*BDIM*40)   // 5120
#define NB_G (BDIM*TDIM)   // 2048
#define NB_T (BDIM*VDIM)   // 1600

__device__ __forceinline__ void attn_body(int wb, char* su) {
    int tid = threadIdx.x;
    int mode = wb / (BDIM*40);
    int rem  = wb % (BDIM*40);
    int bb = rem / 40;
    int wwin = rem % 40;
    int i0 = wwin / 5, i1 = wwin % 5;

    int*    toks = (int*)su;
    float*  sc   = (float*)(su + 320);
    float (*kv)[8][8] = (float(*)[8][8])(su + 960);
    float (*O)[33]    = (float(*)[33])(su + 1984);
    float*  pkv = (float*)(su + 1984);
    __half2 (*Xh)[52] = (__half2(*)[52])(su + 12544);

    if (tid < 80) {
        int a = tid / 10, e = tid % 10;
        int t, v;
        if      (mode == 0) { t = i0*8 + a; v = i1*10 + e; }
        else if (mode == 1) { t = i0*8 + a; v = e*5 + i1;  }
        else if (mode == 2) { t = a*8 + i0; v = i1*10 + e; }
        else                { t = a*8 + i0; v = e*5 + i1;  }
        toks[tid] = (bb*TDIM + t)*VDIM + v;
    }
    __syncthreads();

    int cbh = 128 + mode*96;
    for (int i = tid; i < 80*12; i += 256) {
        int n = i / 12, c = i - n*12;
        uint4 val = *(const uint4*)(h_f + (size_t)toks[n]*C2 + cbh + c*8);
        *(uint4*)&Xh[n][c*4] = val;
    }
    __syncthreads();

    if (tid < 80) {
        float sq = 0.f;
        #pragma unroll 8
        for (int c = 0; c < 48; c++) {
            float2 f = __half22float2(Xh[tid][c]);
            sq += f.x*f.x + f.y*f.y;
        }
        float nrm = fmaxf(sqrtf(sq), 1e-10f);
        float s = tanhf(nrm) / nrm;
        sc[tid] = s;
        float s2 = s*s;
        #pragma unroll
        for (int c = 16; c < 32; c++) {
            float2 f = __half22float2(Xh[tid][c]);
            Xh[tid][c] = __floats2half2_rn(f.x*s2, f.y*s2);
        }
    }
    __syncthreads();

    {
        int slice = tid >> 5;
        int item  = tid & 31;
        int h = item >> 3, d = item & 7;
        int nn0 = slice * 10;
        float acc[8];
        #pragma unroll
        for (int e = 0; e < 8; e++) acc[e] = 0.f;
        #pragma unroll
        for (int n = nn0; n < nn0 + 10; n++) {
            float kd = __half2float(((const __half*)Xh[n])[32 + h*8 + d]);
            float4 vv = *(const float4*)&Xh[n][32 + h*4];
            const __half2* vp = (const __half2*)&vv;
            #pragma unroll
            for (int e2 = 0; e2 < 4; e2++) {
                float2 f = __half22float2(vp[e2]);
                acc[2*e2]   += kd * f.x;
                acc[2*e2+1] += kd * f.y;
            }
        }
        #pragma unroll
        for (int e = 0; e < 8; e++)
            pkv[(e*8 + slice)*32 + item] = acc[e];
    }
    __syncthreads();

    {
        int e = tid >> 5, item = tid & 31;
        int h = item >> 3, d = item & 7;
        float s = 0.f;
        #pragma unroll
        for (int sl = 0; sl < 8; sl++) s += pkv[(e*8 + sl)*32 + item];
        kv[h][d][e] = s;
    }
    __syncthreads();

    if (tid < 32) {
        int h = tid >> 3, d = tid & 7;
        float mx = -1e30f;
        #pragma unroll
        for (int e = 0; e < 8; e++) mx = fmaxf(mx, kv[h][d][e]);
        float s = 0.f;
        #pragma unroll
        for (int e = 0; e < 8; e++) { float q = expf(kv[h][d][e] - mx); s += q; kv[h][d][e] = q; }
        float inv = 1.0f / s;
        #pragma unroll
        for (int e = 0; e < 8; e++) kv[h][d][e] *= inv;
    }
    __syncthreads();

    for (int i = tid; i < 80*16; i += 256) {
        int n = i >> 4, om = i & 15;
        int h = om >> 2, mm2 = om & 3;
        float4 qv = *(const float4*)&Xh[n][h*4];
        const __half2* qp = (const __half2*)&qv;
        float q[8];
        #pragma unroll
        for (int e2 = 0; e2 < 4; e2++) {
            float2 f = __half22float2(qp[e2]);
            q[2*e2] = f.x; q[2*e2+1] = f.y;
        }
        float4 k0 = *(const float4*)&kv[h][2*mm2][0];
        float4 k1 = *(const float4*)&kv[h][2*mm2][4];
        float4 k2 = *(const float4*)&kv[h][2*mm2+1][0];
        float4 k3 = *(const float4*)&kv[h][2*mm2+1][4];
        float a0 = q[0]*k0.x + q[1]*k0.y + q[2]*k0.z + q[3]*k0.w
                 + q[4]*k1.x + q[5]*k1.y + q[6]*k1.z + q[7]*k1.w;
        float a1 = q[0]*k2.x + q[1]*k2.y + q[2]*k2.z + q[3]*k2.w
                 + q[4]*k3.x + q[5]*k3.y + q[6]*k3.z + q[7]*k3.w;
        float s = 0.5f * sc[n];
        O[n][h*8 + 2*mm2]     = s * a0;
        O[n][h*8 + 2*mm2 + 1] = s * a1;
    }
    __syncthreads();

    if (tid < 80) {
        float sq = 0.f;
        #pragma unroll
        for (int c = 0; c < 32; c++) { float q = O[tid][c]; sq += q*q; }
        float nrm = fminf(fmaxf(sqrtf(sq), 1e-10f), 1.0f - 1e-5f);
        float s = atanhf(-nrm) / nrm;
        __half2 pk[16];
        #pragma unroll
        for (int c = 0; c < 16; c++)
            pk[c] = __floats2half2_rn(O[tid][2*c] * s, O[tid][2*c+1] * s);
        uint4* dst = (uint4*)(h_cat + (size_t)toks[tid]*CDIM + 128 + mode*32);
        const uint4* src = (const uint4*)pk;
        #pragma unroll
        for (int c = 0; c < 4; c++) dst[c] = src[c];
    }
}

__device__ __forceinline__ void gconv_body(int bt, const float* __restrict__ gw, char* su) {
    float (*fg)[64] = (float(*)[64])su;
    int tid = threadIdx.x;
    size_t tok0 = (size_t)bt * VDIM;
    for (int i = tid; i < VDIM*8; i += 256) {
        int u = i >> 3, q = i & 7;
        uint4 raw = *(const uint4*)(h_f + (tok0+u)*C2 + q*8);
        const __half2* hp = (const __half2*)&raw;
        float4 lo, hi;
        float2 f0 = __half22float2(hp[0]), f1 = __half22float2(hp[1]);
        float2 f2 = __half22float2(hp[2]), f3 = __half22float2(hp[3]);
        lo.x = f0.x; lo.y = f0.y; lo.z = f1.x; lo.w = f1.y;
        hi.x = f2.x; hi.y = f2.y; hi.z = f3.x; hi.w = f3.y;
        *(float4*)&fg[u][q*8]     = lo;
        *(float4*)&fg[u][q*8 + 4] = hi;
    }
    __syncthreads();
    for (int i = tid; i < VDIM*8; i += 256) {
        int v = i >> 3, g = i & 7;
        const float* gwp = gw + ((size_t)g*VDIM + v)*VDIM;
        float acc[8];
        #pragma unroll
        for (int o = 0; o < 8; o++) acc[o] = 0.f;
        #pragma unroll 5
        for (int u2 = 0; u2 < VDIM/2; u2++) {
            float2 wv = *(const float2*)&gwp[u2*2];
            float4 a0 = *(const float4*)&fg[2*u2][g*8];
            float4 a1 = *(const float4*)&fg[2*u2][g*8+4];
            float4 b0 = *(const float4*)&fg[2*u2+1][g*8];
            float4 b1 = *(const float4*)&fg[2*u2+1][g*8+4];
            acc[0] += wv.x*a0.x + wv.y*b0.x;
            acc[1] += wv.x*a0.y + wv.y*b0.y;
            acc[2] += wv.x*a0.z + wv.y*b0.z;
            acc[3] += wv.x*a0.w + wv.y*b0.w;
            acc[4] += wv.x*a1.x + wv.y*b1.x;
            acc[5] += wv.x*a1.y + wv.y*b1.y;
            acc[6] += wv.x*a1.z + wv.y*b1.z;
            acc[7] += wv.x*a1.w + wv.y*b1.w;
        }
        __half2 pk[4];
        #pragma unroll
        for (int o = 0; o < 4; o++)
            pk[o] = __floats2half2_rn(acc[2*o], acc[2*o+1]);
        *(uint4*)(h_cat + (tok0+v)*CDIM + g*8) = *(const uint4*)pk;
    }
}

__device__ __forceinline__ void tconv_body(int blk, const float* __restrict__ w,
                                           const float* __restrict__ bias, char* su) {
    int bb = blk / VDIM, v = blk % VDIM;
    float (*X)[65] = (float(*)[65])su;
    float* ws = (float*)(su + 16640);
    int tid = threadIdx.x;
    for (int i = tid; i < 64*56; i += 256) {
        int o = i / 56, rr = i % 56;
        ws[rr*64 + o] = w[i];
    }
    for (int i = tid; i < TDIM*8; i += 256) {
        int t = i >> 3, q = i & 7;
        uint4 raw = *(const uint4*)(h_f + ((size_t)(bb*TDIM + t)*VDIM + v)*C2 + 64 + q*8);
        const __half2* hp = (const __half2*)&raw;
        #pragma unroll
        for (int k = 0; k < 4; k++) {
            float2 f = __half22float2(hp[k]);
            X[t][q*8 + 2*k]     = f.x;
            X[t][q*8 + 2*k + 1] = f.y;
        }
    }
    __syncthreads();
    int t = tid & 63, og = tid >> 6;
    size_t tokbase = ((size_t)(bb*TDIM + t)*VDIM + v)*CDIM + 64;
    #pragma unroll
    for (int hg = 0; hg < 2; hg++) {
        int g = og*2 + hg;
        float acc8[8];
        #pragma unroll
        for (int k = 0; k < 8; k++) acc8[k] = bias[g*8 + k];
        #pragma unroll
        for (int dt = 0; dt < 7; dt++) {
            int tt = t + dt - 3;
            if (tt < 0 || tt >= TDIM) continue;
            float xv[8];
            #pragma unroll
            for (int ic = 0; ic < 8; ic++) xv[ic] = X[tt][g*8 + ic];
            #pragma unroll
            for (int ic = 0; ic < 8; ic++) {
                const float* wr = &ws[(ic*7 + dt)*64 + g*8];
                #pragma unroll
                for (int k = 0; k < 8; k++) acc8[k] += xv[ic] * wr[k];
            }
        }
        __half2 pk[4];
        #pragma unroll
        for (int k = 0; k < 4; k++)
            pk[k] = __floats2half2_rn(acc8[2*k], acc8[2*k+1]);
        *(uint4*)(h_cat + tokbase + g*8) = *(const uint4*)pk;
    }
}

__global__ __launch_bounds__(256, 5) void k_branches(const float* __restrict__ gw,
                                                     const float* __restrict__ tw,
                                                     const float* __restrict__ tb) {
    __shared__ __align__(16) char su[31232];
    int bid = blockIdx.x;
    if (bid < NB_A)            attn_body(bid, su);
    else if (bid < NB_A+NB_G)  gconv_body(bid - NB_A, gw, su);
    else                       tconv_body(bid - NB_A - NB_G, tw, tb, su);
}

// ---------------- launch ----------------
extern "C" void kernel_launch(void* const* d_in, const int* in_sizes, int n_in,
                              void* d_out, int out_size) {
    const float* x       = (const float*)d_in[0];
    const float* n1w     = (const float*)d_in[1];
    const float* n1b     = (const float*)d_in[2];
    const float* map_w   = (const float*)d_in[3];
    const float* map_b   = (const float*)d_in[4];
    const float* gconv   = (const float*)d_in[5];
    const float* tconv_w = (const float*)d_in[6];
    const float* tconv_b = (const float*)d_in[7];
    const float* proj_w  = (const float*)d_in[8];
    const float* proj_b  = (const float*)d_in[9];
    const float* n2w     = (const float*)d_in[10];
    const float* n2b     = (const float*)d_in[11];
    const float* mlp_w1  = (const float*)d_in[12];
    const float* mlp_b1  = (const float*)d_in[13];
    const float* mlp_w2  = (const float*)d_in[14];
    const float* mlp_b2  = (const float*)d_in[15];
    float* out = (float*)d_out;

    float *p_out1;
    __half *p_f, *p_xln, *p_cat, *p_ln2, *p_h;
    __half2 *p_wmap, *p_wproj, *p_wm1, *p_wm2;
    cudaGetSymbolAddress((void**)&p_out1, g_out1);
    cudaGetSymbolAddress((void**)&p_f,    h_f);
    cudaGetSymbolAddress((void**)&p_xln,  h_xln);
    cudaGetSymbolAddress((void**)&p_cat,  h_cat);
    cudaGetSymbolAddress((void**)&p_ln2,  h_ln2);
    cudaGetSymbolAddress((void**)&p_h,    h_h);
    cudaGetSymbolAddress((void**)&p_wmap,  w_map);
    cudaGetSymbolAddress((void**)&p_wproj, w_proj);
    cudaGetSymbolAddress((void**)&p_wm1,   w_m1);
    cudaGetSymbolAddress((void**)&p_wm2,   w_m2);

    int wtotal = WS1 + WS2 + WS3 + WS4;
    k_wall<<<(wtotal + 255)/256, 256>>>(map_w, p_wmap, proj_w, p_wproj,
                                        mlp_w1, p_wm1, mlp_w2, p_wm2);
    k_transln<<<BDIM*TDIM, 256>>>(x, n1w, n1b);
    k_gemm_h<3><<<dim3(C2/128, TOK/128), 256>>>(p_xln, p_wmap, map_b, nullptr, p_f, TOK, C2, CDIM);
    k_branches<<<NB_A + NB_G + NB_T, 256>>>(gconv, tconv_w, tconv_b);
    k_gemm_h<5><<<dim3(CDIM/128, TOK/128), 256>>>(p_cat, p_wproj, proj_b, x, p_out1, TOK, CDIM, CDIM);
    k_ln<<<TOK/8, 256>>>(p_out1, p_ln2, n2w, n2b);
    k_gemm_h<2><<<dim3(C4/128, TOK/128), 256>>>(p_ln2, p_wm1, mlp_b1, nullptr, p_h, TOK, C4, CDIM);
    k_gemm_h<4><<<dim3(CDIM/128, TOK/128), 256>>>(p_h, p_wm2, mlp_b2, p_out1, out, TOK, CDIM, C4);
}

// round 16
// speedup vs baseline: 1.0517x; 1.0517x over previous
#include <cuda_runtime.h>
#include <cuda_fp16.h>
#include <math.h>

#define BDIM 32
#define CDIM 256
#define TDIM 64
#define VDIM 50
#define TOK (BDIM*TDIM*VDIM)   // 102400
#define TV  (TDIM*VDIM)        // 3200
#define C2  512
#define C4  1024

// ---------------- scratch ----------------
__device__ float  g_out1[TOK*CDIM];   // proj + skip (fp32)
__device__ __half h_f   [TOK*C2];     // map output (half)
__device__ __half h_xln [TOK*CDIM];
__device__ __half h_cat [TOK*CDIM];
__device__ __half h_ln2 [TOK*CDIM];
__device__ __half h_h   [TOK*C4];
__device__ __half2 w_map [(CDIM/2)*C2];
__device__ __half2 w_proj[(CDIM/2)*CDIM];
__device__ __half2 w_m1  [(CDIM/2)*C4];
__device__ __half2 w_m2  [(C4/2)*CDIM];

__device__ __forceinline__ unsigned sptr(const void* p) {
    return (unsigned)__cvta_generic_to_shared(p);
}
__device__ __forceinline__ void cpa16(unsigned d, const void* s) {
    asm volatile("cp.async.cg.shared.global [%0], [%1], 16;\n" :: "r"(d), "l"(s));
}

// ---------------- merged weight convert ----------------
__device__ __forceinline__ void wpair1(const float* __restrict__ w,
                                       __half2* __restrict__ o, int idx, int N) {
    int k2 = idx / N, n = idx - k2*N;
    o[idx] = __floats2half2_rn(w[(size_t)(2*k2)*N + n], w[(size_t)(2*k2+1)*N + n]);
}
#define WS1 65536
#define WS2 32768
#define WS3 131072
#define WS4 131072
__global__ __launch_bounds__(256) void k_wall(const float* __restrict__ w1, __half2* o1,
                                              const float* __restrict__ w2, __half2* o2,
                                              const float* __restrict__ w3, __half2* o3,
                                              const float* __restrict__ w4, __half2* o4) {
    int idx = blockIdx.x*256 + threadIdx.x;
    if (idx < WS1) { wpair1(w1, o1, idx, C2); return; }
    idx -= WS1;
    if (idx < WS2) { wpair1(w2, o2, idx, CDIM); return; }
    idx -= WS2;
    if (idx < WS3) { wpair1(w3, o3, idx, C4); return; }
    idx -= WS3;
    if (idx < WS4) { wpair1(w4, o4, idx, CDIM); return; }
}

// ---------------- fused transpose + LN1 (h_xln only) ----------------
__global__ __launch_bounds__(256) void k_transln(const float* __restrict__ x,
                                                 const float* __restrict__ w,
                                                 const float* __restrict__ b) {
    int bt = blockIdx.x;
    int bb = bt / TDIM, t = bt % TDIM;
    __shared__ float s[CDIM][51];
    int tid = threadIdx.x, lane = tid & 31, warp = tid >> 5;
    const float* xp = x + (size_t)bb*CDIM*TV + (size_t)t*VDIM;
    for (int i = tid; i < CDIM*VDIM; i += 256) {
        int c = i / VDIM, v = i - c*VDIM;
        s[c][v] = xp[(size_t)c*TV + v];
    }
    __syncthreads();
    size_t tok0 = (size_t)bt*VDIM;
    for (int v = warp; v < VDIM; v += 8) {
        float q[8], s1 = 0.f, s2 = 0.f;
        #pragma unroll
        for (int i = 0; i < 8; i++) {
            q[i] = s[lane + 32*i][v];
            s1 += q[i]; s2 += q[i]*q[i];
        }
        #pragma unroll
        for (int o = 16; o; o >>= 1) {
            s1 += __shfl_xor_sync(0xffffffffu, s1, o);
            s2 += __shfl_xor_sync(0xffffffffu, s2, o);
        }
        float mean = s1 * (1.0f/CDIM);
        float var  = s2 * (1.0f/CDIM) - mean*mean;
        float rstd = rsqrtf(var + 1e-5f);
        size_t base = (tok0 + v)*CDIM;
        #pragma unroll
        for (int i = 0; i < 8; i++) {
            int c = lane + 32*i;
            h_xln[base + c] = __float2half((q[i] - mean) * rstd * w[c] + b[c]);
        }
    }
}

// ---------------- LayerNorm: one token per warp ----------------
__global__ __launch_bounds__(256) void k_ln(const float* __restrict__ src,
                                            __half* __restrict__ dst,
                                            const float* __restrict__ w,
                                            const float* __restrict__ b) {
    size_t m = (size_t)blockIdx.x*8 + (threadIdx.x >> 5);
    int lane = threadIdx.x & 31;
    int c0 = lane*8;
    const float* row = src + m*CDIM + c0;
    float q[8];
    *(float4*)(q)   = *(const float4*)(row);
    *(float4*)(q+4) = *(const float4*)(row + 4);
    float s1 = 0.f, s2 = 0.f;
    #pragma unroll
    for (int i = 0; i < 8; i++) { s1 += q[i]; s2 += q[i]*q[i]; }
    #pragma unroll
    for (int o = 16; o; o >>= 1) {
        s1 += __shfl_xor_sync(0xffffffffu, s1, o);
        s2 += __shfl_xor_sync(0xffffffffu, s2, o);
    }
    float mean = s1 * (1.0f/CDIM);
    float var  = s2 * (1.0f/CDIM) - mean*mean;
    float rstd = rsqrtf(var + 1e-5f);
    float4 wv0 = *(const float4*)&w[c0], wv1 = *(const float4*)&w[c0+4];
    float4 bv0 = *(const float4*)&b[c0], bv1 = *(const float4*)&b[c0+4];
    const float wr[8] = {wv0.x,wv0.y,wv0.z,wv0.w,wv1.x,wv1.y,wv1.z,wv1.w};
    const float br[8] = {bv0.x,bv0.y,bv0.z,bv0.w,bv1.x,bv1.y,bv1.z,bv1.w};
    __half2 pk[4];
    #pragma unroll
    for (int i = 0; i < 4; i++) {
        float v0 = (q[2*i]   - mean) * rstd * wr[2*i]   + br[2*i];
        float v1 = (q[2*i+1] - mean) * rstd * wr[2*i+1] + br[2*i+1];
        pk[i] = __floats2half2_rn(v0, v1);
    }
    *(uint4*)(dst + m*CDIM + c0) = *(const uint4*)pk;
}

// ---------------- fp16 tensor-core GEMM 128x128x32, cp.async 3-stage ----------------
// EPI: 2 bias+gelu->half | 3 bias->half
//      4 bias+extra(out1) -> transposed store to (B,C,T,V) fp32 out
//      5 bias + skip read directly from x (B,C,T,V) -> f32 out
#define SA 40
#define SB 136
template<int EPI>
__global__ __launch_bounds__(256, 2) void k_gemm_h(const __half* __restrict__ A,
                                                   const __half2* __restrict__ Bp,
                                                   const float* __restrict__ bias,
                                                   const float* __restrict__ extra,
                                                   void* __restrict__ Cout,
                                                   int M, int N, int K) {
    __shared__ __align__(16) __half  As[3][128*SA];
    __shared__ __align__(16) __half2 Bs[3][16*SB];
    int tid = threadIdx.x, lane = tid & 31, warp = tid >> 5;
    int wm = warp >> 2, wn = warp & 3;
    int m0 = blockIdx.y * 128, n0 = blockIdx.x * 128;
    int r = lane >> 2, c = lane & 3;

    float acc[4][4][4];
    #pragma unroll
    for (int i = 0; i < 4; i++)
        #pragma unroll
        for (int j = 0; j < 4; j++)
            #pragma unroll
            for (int q = 0; q < 4; q++) acc[i][j][q] = 0.f;

    auto stage = [&](int s, int k0) {
        #pragma unroll
        for (int hh = 0; hh < 2; hh++) {
            int ch = tid + hh*256;
            int row = ch >> 2, seg = ch & 3;
            cpa16(sptr(&As[s][row*SA + seg*8]),
                  A + (size_t)(m0+row)*K + k0 + seg*8);
        }
        int k20 = k0 >> 1;
        #pragma unroll
        for (int hh = 0; hh < 2; hh++) {
            int ch = tid + hh*256;
            int k2 = ch >> 5, seg = ch & 31;
            cpa16(sptr(&Bs[s][k2*SB + seg*4]),
                  Bp + (size_t)(k20+k2)*N + n0 + seg*4);
        }
    };

    int nt = K >> 5;
    stage(0, 0);
    asm volatile("cp.async.commit_group;\n");
    stage(1, 32);
    asm volatile("cp.async.commit_group;\n");

    int lrow = (lane & 7) + ((lane >> 3) & 1)*8;
    int lcol = ((lane >> 4) & 1)*8;

    for (int t = 0; t < nt; t++) {
        if (t+1 < nt) asm volatile("cp.async.wait_group 1;\n");
        else          asm volatile("cp.async.wait_group 0;\n");
        __syncthreads();
        int s = t % 3;
        #pragma unroll
        for (int kk = 0; kk < 32; kk += 16) {
            unsigned af[4][4];
            #pragma unroll
            for (int i = 0; i < 4; i++) {
                int row = wm*64 + i*16 + lrow;
                unsigned ad = sptr(&As[s][row*SA + kk + lcol]);
                asm volatile("ldmatrix.sync.aligned.m8n8.x4.shared.b16 {%0,%1,%2,%3}, [%4];"
                    : "=r"(af[i][0]), "=r"(af[i][1]), "=r"(af[i][2]), "=r"(af[i][3])
                    : "r"(ad));
            }
            int kk2 = kk >> 1;
            unsigned bf[4][2];
            #pragma unroll
            for (int j = 0; j < 4; j++) {
                int nb = wn*32 + j*8 + r;
                bf[j][0] = *(const unsigned*)&Bs[s][(kk2+c  )*SB + nb];
                bf[j][1] = *(const unsigned*)&Bs[s][(kk2+c+4)*SB + nb];
            }
            #pragma unroll
            for (int i = 0; i < 4; i++)
                #pragma unroll
                for (int j = 0; j < 4; j++) {
                    asm volatile(
                        "mma.sync.aligned.m16n8k16.row.col.f32.f16.f16.f32 "
                        "{%0,%1,%2,%3}, {%4,%5,%6,%7}, {%8,%9}, {%0,%1,%2,%3};"
                        : "+f"(acc[i][j][0]), "+f"(acc[i][j][1]),
                          "+f"(acc[i][j][2]), "+f"(acc[i][j][3])
                        : "r"(af[i][0]), "r"(af[i][1]), "r"(af[i][2]), "r"(af[i][3]),
                          "r"(bf[j][0]), "r"(bf[j][1]));
                }
        }
        if (t+2 < nt) {
            stage((t+2) % 3, (t+2)*32);
            asm volatile("cp.async.commit_group;\n");
        }
    }

    if (EPI == 4) {
        float* tb = (float*)&As[0][0];
        int bidx = m0 / TV;
        int rem0 = m0 % TV;
        #pragma unroll 1
        for (int wmt = 0; wmt < 2; wmt++) {
            #pragma unroll 1
            for (int i = 0; i < 4; i++) {
                __syncthreads();
                if (wm == wmt) {
                    #pragma unroll
                    for (int j = 0; j < 4; j++) {
                        int colb = wn*32 + j*8 + c*2;
                        float b0 = bias[n0+colb], b1 = bias[n0+colb+1];
                        #pragma unroll
                        for (int hh = 0; hh < 2; hh++) {
                            int rl = r + hh*8;
                            size_t mrow = (size_t)(m0 + wmt*64 + i*16 + rl);
                            const float2 e = *(const float2*)&extra[mrow*N + n0 + colb];
                            tb[colb*20 + rl]     = acc[i][j][2*hh]   + b0 + e.x;
                            tb[(colb+1)*20 + rl] = acc[i][j][2*hh+1] + b1 + e.y;
                        }
                    }
                }
                __syncthreads();
                int col = tid >> 1, rh = tid & 1;
                int cg = n0 + col;
                int rowbase = wmt*64 + i*16 + rh*8;
                float4 o1 = *(float4*)&tb[col*20 + rh*8];
                float4 o2 = *(float4*)&tb[col*20 + rh*8 + 4];
                size_t oaddr = (size_t)bidx*CDIM*TV + (size_t)cg*TV + rem0 + rowbase;
                *(float4*)&((float*)Cout)[oaddr]     = o1;
                *(float4*)&((float*)Cout)[oaddr + 4] = o2;
            }
        }
        return;
    }

    int bq = m0 / TV, rq = m0 % TV;
    #pragma unroll
    for (int i = 0; i < 4; i++) {
        #pragma unroll
        for (int j = 0; j < 4; j++) {
            int row0 = m0 + wm*64 + i*16 + r;
            int col  = n0 + wn*32 + j*8 + c*2;
            float b0 = bias[col], b1 = bias[col+1];
            #pragma unroll
            for (int hh = 0; hh < 2; hh++) {
                size_t mrow = (size_t)(row0 + hh*8);
                float v0 = acc[i][j][2*hh+0] + b0;
                float v1 = acc[i][j][2*hh+1] + b1;
                if (EPI == 5) {
                    int local = wm*64 + i*16 + r + hh*8;
                    size_t xoff = (size_t)(bq*CDIM + col)*TV + rq + local;
                    v0 += extra[xoff];
                    v1 += extra[xoff + TV];
                }
                if (EPI == 2) {
                    v0 = 0.5f * v0 * (1.0f + erff(v0 * 0.70710678118654752f));
                    v1 = 0.5f * v1 * (1.0f + erff(v1 * 0.70710678118654752f));
                }
                if (EPI == 2 || EPI == 3) {
                    *(__half2*)((__half*)Cout + mrow*N + col) = __floats2half2_rn(v0, v1);
                } else {
                    float2 o; o.x = v0; o.y = v1;
                    *(float2*)((float*)Cout + mrow*N + col) = o;
                }
            }
        }
    }
}

// ---------------- merged branches ----------------
#define NB_A (4*BDIM*40)   // 5120
#define NB_G (BDIM*TDIM)   // 2048
#define NB_T (BDIM*VDIM)   // 1600

__device__ __forceinline__ void attn_body(int wb, char* su) {
    int tid = threadIdx.x;
    int mode = wb / (BDIM*40);
    int rem  = wb % (BDIM*40);
    int bb = rem / 40;
    int wwin = rem % 40;
    int i0 = wwin / 5, i1 = wwin % 5;

    int*    toks = (int*)su;
    float*  sc   = (float*)(su + 320);
    float (*kv)[8][8] = (float(*)[8][8])(su + 960);
    float (*O)[33]    = (float(*)[33])(su + 1984);
    float*  pkv = (float*)(su + 1984);
    __half2 (*Xh)[52] = (__half2(*)[52])(su + 12544);

    if (tid < 80) {
        int a = tid / 10, e = tid % 10;
        int t, v;
        if      (mode == 0) { t = i0*8 + a; v = i1*10 + e; }
        else if (mode == 1) { t = i0*8 + a; v = e*5 + i1;  }
        else if (mode == 2) { t = a*8 + i0; v = i1*10 + e; }
        else                { t = a*8 + i0; v = e*5 + i1;  }
        toks[tid] = (bb*TDIM + t)*VDIM + v;
    }
    __syncthreads();

    int cbh = 128 + mode*96;
    for (int i = tid; i < 80*12; i += 256) {
        int n = i / 12, c = i - n*12;
        uint4 val = *(const uint4*)(h_f + (size_t)toks[n]*C2 + cbh + c*8);
        *(uint4*)&Xh[n][c*4] = val;
    }
    __syncthreads();

    if (tid < 80) {
        float sq = 0.f;
        #pragma unroll 8
        for (int c = 0; c < 48; c++) {
            float2 f = __half22float2(Xh[tid][c]);
            sq += f.x*f.x + f.y*f.y;
        }
        float nrm = fmaxf(sqrtf(sq), 1e-10f);
        float s = tanhf(nrm) / nrm;
        sc[tid] = s;
        float s2 = s*s;
        #pragma unroll
        for (int c = 16; c < 32; c++) {
            float2 f = __half22float2(Xh[tid][c]);
            Xh[tid][c] = __floats2half2_rn(f.x*s2, f.y*s2);
        }
    }
    __syncthreads();

    {
        int slice = tid >> 5;
        int item  = tid & 31;
        int h = item >> 3, d = item & 7;
        int nn0 = slice * 10;
        float acc[8];
        #pragma unroll
        for (int e = 0; e < 8; e++) acc[e] = 0.f;
        #pragma unroll
        for (int n = nn0; n < nn0 + 10; n++) {
            float kd = __half2float(((const __half*)Xh[n])[32 + h*8 + d]);
            float4 vv = *(const float4*)&Xh[n][32 + h*4];
            const __half2* vp = (const __half2*)&vv;
            #pragma unroll
            for (int e2 = 0; e2 < 4; e2++) {
                float2 f = __half22float2(vp[e2]);
                acc[2*e2]   += kd * f.x;
                acc[2*e2+1] += kd * f.y;
            }
        }
        #pragma unroll
        for (int e = 0; e < 8; e++)
            pkv[(e*8 + slice)*32 + item] = acc[e];
    }
    __syncthreads();

    {
        int e = tid >> 5, item = tid & 31;
        int h = item >> 3, d = item & 7;
        float s = 0.f;
        #pragma unroll
        for (int sl = 0; sl < 8; sl++) s += pkv[(e*8 + sl)*32 + item];
        kv[h][d][e] = s;
    }
    __syncthreads();

    if (tid < 32) {
        int h = tid >> 3, d = tid & 7;
        float mx = -1e30f;
        #pragma unroll
        for (int e = 0; e < 8; e++) mx = fmaxf(mx, kv[h][d][e]);
        float s = 0.f;
        #pragma unroll
        for (int e = 0; e < 8; e++) { float q = expf(kv[h][d][e] - mx); s += q; kv[h][d][e] = q; }
        float inv = 1.0f / s;
        #pragma unroll
        for (int e = 0; e < 8; e++) kv[h][d][e] *= inv;
    }
    __syncthreads();

    for (int i = tid; i < 80*16; i += 256) {
        int n = i >> 4, om = i & 15;
        int h = om >> 2, mm2 = om & 3;
        float4 qv = *(const float4*)&Xh[n][h*4];
        const __half2* qp = (const __half2*)&qv;
        float q[8];
        #pragma unroll
        for (int e2 = 0; e2 < 4; e2++) {
            float2 f = __half22float2(qp[e2]);
            q[2*e2] = f.x; q[2*e2+1] = f.y;
        }
        float4 k0 = *(const float4*)&kv[h][2*mm2][0];
        float4 k1 = *(const float4*)&kv[h][2*mm2][4];
        float4 k2 = *(const float4*)&kv[h][2*mm2+1][0];
        float4 k3 = *(const float4*)&kv[h][2*mm2+1][4];
        float a0 = q[0]*k0.x + q[1]*k0.y + q[2]*k0.z + q[3]*k0.w
                 + q[4]*k1.x + q[5]*k1.y + q[6]*k1.z + q[7]*k1.w;
        float a1 = q[0]*k2.x + q[1]*k2.y + q[2]*k2.z + q[3]*k2.w
                 + q[4]*k3.x + q[5]*k3.y + q[6]*k3.z + q[7]*k3.w;
        float s = 0.5f * sc[n];
        O[n][h*8 + 2*mm2]     = s * a0;
        O[n][h*8 + 2*mm2 + 1] = s * a1;
    }
    __syncthreads();

    if (tid < 80) {
        float sq = 0.f;
        #pragma unroll
        for (int c = 0; c < 32; c++) { float q = O[tid][c]; sq += q*q; }
        float nrm = fminf(fmaxf(sqrtf(sq), 1e-10f), 1.0f - 1e-5f);
        float s = atanhf(-nrm) / nrm;
        __half2 pk[16];
        #pragma unroll
        for (int c = 0; c < 16; c++)
            pk[c] = __floats2half2_rn(O[tid][2*c] * s, O[tid][2*c+1] * s);
        uint4* dst = (uint4*)(h_cat + (size_t)toks[tid]*CDIM + 128 + mode*32);
        const uint4* src = (const uint4*)pk;
        #pragma unroll
        for (int c = 0; c < 4; c++) dst[c] = src[c];
    }
}

__device__ __forceinline__ void gconv_body(int bt, const float* __restrict__ gw, char* su) {
    __half2 (*fg)[36] = (__half2(*)[36])su;   // 50 x 36 half2 = 7200 B
    int tid = threadIdx.x;
    size_t tok0 = (size_t)bt * VDIM;
    for (int i = tid; i < VDIM*8; i += 256) {
        int u = i >> 3, q = i & 7;
        *(uint4*)&fg[u][q*4] = *(const uint4*)(h_f + (tok0+u)*C2 + q*8);
    }
    __syncthreads();
    for (int i = tid; i < VDIM*8; i += 256) {
        int v = i >> 3, g = i & 7;
        const float* gwp = gw + ((size_t)g*VDIM + v)*VDIM;
        float acc[8];
        #pragma unroll
        for (int o = 0; o < 8; o++) acc[o] = 0.f;
        #pragma unroll 5
        for (int u2 = 0; u2 < VDIM/2; u2++) {
            float2 wv = *(const float2*)&gwp[u2*2];
            uint4 ra = *(const uint4*)&fg[2*u2][g*4];
            uint4 rb = *(const uint4*)&fg[2*u2+1][g*4];
            const __half2* pa = (const __half2*)&ra;
            const __half2* pb = (const __half2*)&rb;
            #pragma unroll
            for (int p = 0; p < 4; p++) {
                float2 fa = __half22float2(pa[p]);
                float2 fb = __half22float2(pb[p]);
                acc[2*p]   += wv.x*fa.x + wv.y*fb.x;
                acc[2*p+1] += wv.x*fa.y + wv.y*fb.y;
            }
        }
        __half2 pk[4];
        #pragma unroll
        for (int o = 0; o < 4; o++)
            pk[o] = __floats2half2_rn(acc[2*o], acc[2*o+1]);
        *(uint4*)(h_cat + (tok0+v)*CDIM + g*8) = *(const uint4*)pk;
    }
}

__device__ __forceinline__ void tconv_body(int blk, const float* __restrict__ w,
                                           const float* __restrict__ bias, char* su) {
    int bb = blk / VDIM, v = blk % VDIM;
    __half2 (*X)[36] = (__half2(*)[36])su;    // 64 x 36 half2 = 9216 B
    float* ws = (float*)(su + 9216);          // 56*64*4 = 14336 B
    int tid = threadIdx.x;
    for (int i = tid; i < 64*56; i += 256) {
        int o = i / 56, rr = i % 56;
        ws[rr*64 + o] = w[i];
    }
    for (int i = tid; i < TDIM*8; i += 256) {
        int t = i >> 3, q = i & 7;
        *(uint4*)&X[t][q*4] =
            *(const uint4*)(h_f + ((size_t)(bb*TDIM + t)*VDIM + v)*C2 + 64 + q*8);
    }
    __syncthreads();
    int t = tid & 63, og = tid >> 6;
    size_t tokbase = ((size_t)(bb*TDIM + t)*VDIM + v)*CDIM + 64;
    #pragma unroll
    for (int hg = 0; hg < 2; hg++) {
        int g = og*2 + hg;
        float acc8[8];
        #pragma unroll
        for (int k = 0; k < 8; k++) acc8[k] = bias[g*8 + k];
        #pragma unroll
        for (int dt = 0; dt < 7; dt++) {
            int tt = t + dt - 3;
            if (tt < 0 || tt >= TDIM) continue;
            uint4 raw = *(const uint4*)&X[tt][g*4];
            const __half2* hp = (const __half2*)&raw;
            float xv[8];
            #pragma unroll
            for (int p = 0; p < 4; p++) {
                float2 f = __half22float2(hp[p]);
                xv[2*p] = f.x; xv[2*p+1] = f.y;
            }
            #pragma unroll
            for (int ic = 0; ic < 8; ic++) {
                const float* wr = &ws[(ic*7 + dt)*64 + g*8];
                #pragma unroll
                for (int k = 0; k < 8; k++) acc8[k] += xv[ic] * wr[k];
            }
        }
        __half2 pk[4];
        #pragma unroll
        for (int k = 0; k < 4; k++)
            pk[k] = __floats2half2_rn(acc8[2*k], acc8[2*k+1]);
        *(uint4*)(h_cat + tokbase + g*8) = *(const uint4*)pk;
    }
}

__global__ __launch_bounds__(256) void k_branches(const float* __restrict__ gw,
                                                  const float* __restrict__ tw,
                                                  const float* __restrict__ tb) {
    __shared__ __align__(16) char su[31232];
    int bid = blockIdx.x;
    if (bid < NB_A)            attn_body(bid, su);
    else if (bid < NB_A+NB_G)  gconv_body(bid - NB_A, gw, su);
    else                       tconv_body(bid - NB_A - NB_G, tw, tb, su);
}

// ---------------- launch ----------------
extern "C" void kernel_launch(void* const* d_in, const int* in_sizes, int n_in,
                              void* d_out, int out_size) {
    const float* x       = (const float*)d_in[0];
    const float* n1w     = (const float*)d_in[1];
    const float* n1b     = (const float*)d_in[2];
    const float* map_w   = (const float*)d_in[3];
    const float* map_b   = (const float*)d_in[4];
    const float* gconv   = (const float*)d_in[5];
    const float* tconv_w = (const float*)d_in[6];
    const float* tconv_b = (const float*)d_in[7];
    const float* proj_w  = (const float*)d_in[8];
    const float* proj_b  = (const float*)d_in[9];
    const float* n2w     = (const float*)d_in[10];
    const float* n2b     = (const float*)d_in[11];
    const float* mlp_w1  = (const float*)d_in[12];
    const float* mlp_b1  = (const float*)d_in[13];
    const float* mlp_w2  = (const float*)d_in[14];
    const float* mlp_b2  = (const float*)d_in[15];
    float* out = (float*)d_out;

    float *p_out1;
    __half *p_f, *p_xln, *p_cat, *p_ln2, *p_h;
    __half2 *p_wmap, *p_wproj, *p_wm1, *p_wm2;
    cudaGetSymbolAddress((void**)&p_out1, g_out1);
    cudaGetSymbolAddress((void**)&p_f,    h_f);
    cudaGetSymbolAddress((void**)&p_xln,  h_xln);
    cudaGetSymbolAddress((void**)&p_cat,  h_cat);
    cudaGetSymbolAddress((void**)&p_ln2,  h_ln2);
    cudaGetSymbolAddress((void**)&p_h,    h_h);
    cudaGetSymbolAddress((void**)&p_wmap,  w_map);
    cudaGetSymbolAddress((void**)&p_wproj, w_proj);
    cudaGetSymbolAddress((void**)&p_wm1,   w_m1);
    cudaGetSymbolAddress((void**)&p_wm2,   w_m2);

    int wtotal = WS1 + WS2 + WS3 + WS4;
    k_wall<<<(wtotal + 255)/256, 256>>>(map_w, p_wmap, proj_w, p_wproj,
                                        mlp_w1, p_wm1, mlp_w2, p_wm2);
    k_transln<<<BDIM*TDIM, 256>>>(x, n1w, n1b);
    k_gemm_h<3><<<dim3(C2/128, TOK/128), 256>>>(p_xln, p_wmap, map_b, nullptr, p_f, TOK, C2, CDIM);
    k_branches<<<NB_A + NB_G + NB_T, 256>>>(gconv, tconv_w, tconv_b);
    k_gemm_h<5><<<dim3(CDIM/128, TOK/128), 256>>>(p_cat, p_wproj, proj_b, x, p_out1, TOK, CDIM, CDIM);
    k_ln<<<TOK/8, 256>>>(p_out1, p_ln2, n2w, n2b);
    k_gemm_h<2><<<dim3(C4/128, TOK/128), 256>>>(p_ln2, p_wm1, mlp_b1, nullptr, p_h, TOK, C4, CDIM);
    k_gemm_h<4><<<dim3(CDIM/128, TOK/128), 256>>>(p_h, p_wm2, mlp_b2, p_out1, out, TOK, CDIM, C4);
}

// round 17
// speedup vs baseline: 1.0563x; 1.0044x over previous
#include <cuda_runtime.h>
#include <cuda_fp16.h>
#include <math.h>

#define BDIM 32
#define CDIM 256
#define TDIM 64
#define VDIM 50
#define TOK (BDIM*TDIM*VDIM)   // 102400
#define TV  (TDIM*VDIM)        // 3200
#define C2  512
#define C4  1024

// ---------------- scratch ----------------
__device__ float  g_out1[TOK*CDIM];   // proj + skip (fp32)
__device__ __half h_f   [TOK*C2];     // map output (half)
__device__ __half h_xln [TOK*CDIM];
__device__ __half h_cat [TOK*CDIM];
__device__ __half h_ln2 [TOK*CDIM];
__device__ __half h_h   [TOK*C4];
__device__ __half2 w_map [(CDIM/2)*C2];
__device__ __half2 w_proj[(CDIM/2)*CDIM];
__device__ __half2 w_m1  [(CDIM/2)*C4];
__device__ __half2 w_m2  [(C4/2)*CDIM];

__device__ __forceinline__ unsigned sptr(const void* p) {
    return (unsigned)__cvta_generic_to_shared(p);
}
__device__ __forceinline__ void cpa16(unsigned d, const void* s) {
    asm volatile("cp.async.cg.shared.global [%0], [%1], 16;\n" :: "r"(d), "l"(s));
}

// ---------------- merged weight convert ----------------
__device__ __forceinline__ void wpair1(const float* __restrict__ w,
                                       __half2* __restrict__ o, int idx, int N) {
    int k2 = idx / N, n = idx - k2*N;
    o[idx] = __floats2half2_rn(w[(size_t)(2*k2)*N + n], w[(size_t)(2*k2+1)*N + n]);
}
#define WS1 65536
#define WS2 32768
#define WS3 131072
#define WS4 131072
__global__ __launch_bounds__(256) void k_wall(const float* __restrict__ w1, __half2* o1,
                                              const float* __restrict__ w2, __half2* o2,
                                              const float* __restrict__ w3, __half2* o3,
                                              const float* __restrict__ w4, __half2* o4) {
    int idx = blockIdx.x*256 + threadIdx.x;
    if (idx < WS1) { wpair1(w1, o1, idx, C2); return; }
    idx -= WS1;
    if (idx < WS2) { wpair1(w2, o2, idx, CDIM); return; }
    idx -= WS2;
    if (idx < WS3) { wpair1(w3, o3, idx, C4); return; }
    idx -= WS3;
    if (idx < WS4) { wpair1(w4, o4, idx, CDIM); return; }
}

// ---------------- fused transpose + LN1 (float2 global loads) ----------------
__global__ __launch_bounds__(256) void k_transln(const float* __restrict__ x,
                                                 const float* __restrict__ w,
                                                 const float* __restrict__ b) {
    int bt = blockIdx.x;
    int bb = bt / TDIM, t = bt % TDIM;
    __shared__ float s[CDIM][51];
    int tid = threadIdx.x, lane = tid & 31, warp = tid >> 5;
    const float* xp = x + (size_t)bb*CDIM*TV + (size_t)t*VDIM;
    // 256 channels x 25 float2 pairs (8B-aligned: t*50*4 = 200B, c*TV*4 = 12800B)
    for (int i = tid; i < CDIM*25; i += 256) {
        int c = i / 25, p = i - c*25;
        float2 f = *(const float2*)(xp + (size_t)c*TV + p*2);
        s[c][p*2]   = f.x;
        s[c][p*2+1] = f.y;
    }
    __syncthreads();
    size_t tok0 = (size_t)bt*VDIM;
    for (int v = warp; v < VDIM; v += 8) {
        float q[8], s1 = 0.f, s2 = 0.f;
        #pragma unroll
        for (int i = 0; i < 8; i++) {
            q[i] = s[lane + 32*i][v];
            s1 += q[i]; s2 += q[i]*q[i];
        }
        #pragma unroll
        for (int o = 16; o; o >>= 1) {
            s1 += __shfl_xor_sync(0xffffffffu, s1, o);
            s2 += __shfl_xor_sync(0xffffffffu, s2, o);
        }
        float mean = s1 * (1.0f/CDIM);
        float var  = s2 * (1.0f/CDIM) - mean*mean;
        float rstd = rsqrtf(var + 1e-5f);
        size_t base = (tok0 + v)*CDIM;
        #pragma unroll
        for (int i = 0; i < 8; i++) {
            int c = lane + 32*i;
            h_xln[base + c] = __float2half((q[i] - mean) * rstd * w[c] + b[c]);
        }
    }
}

// ---------------- LayerNorm: one token per warp ----------------
__global__ __launch_bounds__(256) void k_ln(const float* __restrict__ src,
                                            __half* __restrict__ dst,
                                            const float* __restrict__ w,
                                            const float* __restrict__ b) {
    size_t m = (size_t)blockIdx.x*8 + (threadIdx.x >> 5);
    int lane = threadIdx.x & 31;
    int c0 = lane*8;
    const float* row = src + m*CDIM + c0;
    float q[8];
    *(float4*)(q)   = *(const float4*)(row);
    *(float4*)(q+4) = *(const float4*)(row + 4);
    float s1 = 0.f, s2 = 0.f;
    #pragma unroll
    for (int i = 0; i < 8; i++) { s1 += q[i]; s2 += q[i]*q[i]; }
    #pragma unroll
    for (int o = 16; o; o >>= 1) {
        s1 += __shfl_xor_sync(0xffffffffu, s1, o);
        s2 += __shfl_xor_sync(0xffffffffu, s2, o);
    }
    float mean = s1 * (1.0f/CDIM);
    float var  = s2 * (1.0f/CDIM) - mean*mean;
    float rstd = rsqrtf(var + 1e-5f);
    float4 wv0 = *(const float4*)&w[c0], wv1 = *(const float4*)&w[c0+4];
    float4 bv0 = *(const float4*)&b[c0], bv1 = *(const float4*)&b[c0+4];
    const float wr[8] = {wv0.x,wv0.y,wv0.z,wv0.w,wv1.x,wv1.y,wv1.z,wv1.w};
    const float br[8] = {bv0.x,bv0.y,bv0.z,bv0.w,bv1.x,bv1.y,bv1.z,bv1.w};
    __half2 pk[4];
    #pragma unroll
    for (int i = 0; i < 4; i++) {
        float v0 = (q[2*i]   - mean) * rstd * wr[2*i]   + br[2*i];
        float v1 = (q[2*i+1] - mean) * rstd * wr[2*i+1] + br[2*i+1];
        pk[i] = __floats2half2_rn(v0, v1);
    }
    *(uint4*)(dst + m*CDIM + c0) = *(const uint4*)pk;
}

// ---------------- fp16 tensor-core GEMM 128x128x32, cp.async 3-stage ----------------
// EPI: 2 bias+gelu->half | 3 bias->half
//      4 bias+extra(out1) -> transposed store to (B,C,T,V) fp32 out
//      5 bias + skip read directly from x (B,C,T,V) -> f32 out
#define SA 40
#define SB 136
template<int EPI>
__global__ __launch_bounds__(256, 2) void k_gemm_h(const __half* __restrict__ A,
                                                   const __half2* __restrict__ Bp,
                                                   const float* __restrict__ bias,
                                                   const float* __restrict__ extra,
                                                   void* __restrict__ Cout,
                                                   int M, int N, int K) {
    __shared__ __align__(16) __half  As[3][128*SA];
    __shared__ __align__(16) __half2 Bs[3][16*SB];
    int tid = threadIdx.x, lane = tid & 31, warp = tid >> 5;
    int wm = warp >> 2, wn = warp & 3;
    int m0 = blockIdx.y * 128, n0 = blockIdx.x * 128;
    int r = lane >> 2, c = lane & 3;

    float acc[4][4][4];
    #pragma unroll
    for (int i = 0; i < 4; i++)
        #pragma unroll
        for (int j = 0; j < 4; j++)
            #pragma unroll
            for (int q = 0; q < 4; q++) acc[i][j][q] = 0.f;

    auto stage = [&](int s, int k0) {
        #pragma unroll
        for (int hh = 0; hh < 2; hh++) {
            int ch = tid + hh*256;
            int row = ch >> 2, seg = ch & 3;
            cpa16(sptr(&As[s][row*SA + seg*8]),
                  A + (size_t)(m0+row)*K + k0 + seg*8);
        }
        int k20 = k0 >> 1;
        #pragma unroll
        for (int hh = 0; hh < 2; hh++) {
            int ch = tid + hh*256;
            int k2 = ch >> 5, seg = ch & 31;
            cpa16(sptr(&Bs[s][k2*SB + seg*4]),
                  Bp + (size_t)(k20+k2)*N + n0 + seg*4);
        }
    };

    int nt = K >> 5;
    stage(0, 0);
    asm volatile("cp.async.commit_group;\n");
    stage(1, 32);
    asm volatile("cp.async.commit_group;\n");

    int lrow = (lane & 7) + ((lane >> 3) & 1)*8;
    int lcol = ((lane >> 4) & 1)*8;

    for (int t = 0; t < nt; t++) {
        if (t+1 < nt) asm volatile("cp.async.wait_group 1;\n");
        else          asm volatile("cp.async.wait_group 0;\n");
        __syncthreads();
        int s = t % 3;
        #pragma unroll
        for (int kk = 0; kk < 32; kk += 16) {
            unsigned af[4][4];
            #pragma unroll
            for (int i = 0; i < 4; i++) {
                int row = wm*64 + i*16 + lrow;
                unsigned ad = sptr(&As[s][row*SA + kk + lcol]);
                asm volatile("ldmatrix.sync.aligned.m8n8.x4.shared.b16 {%0,%1,%2,%3}, [%4];"
                    : "=r"(af[i][0]), "=r"(af[i][1]), "=r"(af[i][2]), "=r"(af[i][3])
                    : "r"(ad));
            }
            int kk2 = kk >> 1;
            unsigned bf[4][2];
            #pragma unroll
            for (int j = 0; j < 4; j++) {
                int nb = wn*32 + j*8 + r;
                bf[j][0] = *(const unsigned*)&Bs[s][(kk2+c  )*SB + nb];
                bf[j][1] = *(const unsigned*)&Bs[s][(kk2+c+4)*SB + nb];
            }
            #pragma unroll
            for (int i = 0; i < 4; i++)
                #pragma unroll
                for (int j = 0; j < 4; j++) {
                    asm volatile(
                        "mma.sync.aligned.m16n8k16.row.col.f32.f16.f16.f32 "
                        "{%0,%1,%2,%3}, {%4,%5,%6,%7}, {%8,%9}, {%0,%1,%2,%3};"
                        : "+f"(acc[i][j][0]), "+f"(acc[i][j][1]),
                          "+f"(acc[i][j][2]), "+f"(acc[i][j][3])
                        : "r"(af[i][0]), "r"(af[i][1]), "r"(af[i][2]), "r"(af[i][3]),
                          "r"(bf[j][0]), "r"(bf[j][1]));
                }
        }
        if (t+2 < nt) {
            stage((t+2) % 3, (t+2)*32);
            asm volatile("cp.async.commit_group;\n");
        }
    }

    if (EPI == 4) {
        float* tb = (float*)&As[0][0];
        int bidx = m0 / TV;
        int rem0 = m0 % TV;
        #pragma unroll 1
        for (int wmt = 0; wmt < 2; wmt++) {
            #pragma unroll 1
            for (int i = 0; i < 4; i++) {
                __syncthreads();
                if (wm == wmt) {
                    #pragma unroll
                    for (int j = 0; j < 4; j++) {
                        int colb = wn*32 + j*8 + c*2;
                        float b0 = bias[n0+colb], b1 = bias[n0+colb+1];
                        #pragma unroll
                        for (int hh = 0; hh < 2; hh++) {
                            int rl = r + hh*8;
                            size_t mrow = (size_t)(m0 + wmt*64 + i*16 + rl);
                            const float2 e = *(const float2*)&extra[mrow*N + n0 + colb];
                            tb[colb*20 + rl]     = acc[i][j][2*hh]   + b0 + e.x;
                            tb[(colb+1)*20 + rl] = acc[i][j][2*hh+1] + b1 + e.y;
                        }
                    }
                }
                __syncthreads();
                int col = tid >> 1, rh = tid & 1;
                int cg = n0 + col;
                int rowbase = wmt*64 + i*16 + rh*8;
                float4 o1 = *(float4*)&tb[col*20 + rh*8];
                float4 o2 = *(float4*)&tb[col*20 + rh*8 + 4];
                size_t oaddr = (size_t)bidx*CDIM*TV + (size_t)cg*TV + rem0 + rowbase;
                *(float4*)&((float*)Cout)[oaddr]     = o1;
                *(float4*)&((float*)Cout)[oaddr + 4] = o2;
            }
        }
        return;
    }

    int bq = m0 / TV, rq = m0 % TV;
    #pragma unroll
    for (int i = 0; i < 4; i++) {
        #pragma unroll
        for (int j = 0; j < 4; j++) {
            int row0 = m0 + wm*64 + i*16 + r;
            int col  = n0 + wn*32 + j*8 + c*2;
            float b0 = bias[col], b1 = bias[col+1];
            #pragma unroll
            for (int hh = 0; hh < 2; hh++) {
                size_t mrow = (size_t)(row0 + hh*8);
                float v0 = acc[i][j][2*hh+0] + b0;
                float v1 = acc[i][j][2*hh+1] + b1;
                if (EPI == 5) {
                    int local = wm*64 + i*16 + r + hh*8;
                    size_t xoff = (size_t)(bq*CDIM + col)*TV + rq + local;
                    v0 += extra[xoff];
                    v1 += extra[xoff + TV];
                }
                if (EPI == 2) {
                    v0 = 0.5f * v0 * (1.0f + erff(v0 * 0.70710678118654752f));
                    v1 = 0.5f * v1 * (1.0f + erff(v1 * 0.70710678118654752f));
                }
                if (EPI == 2 || EPI == 3) {
                    *(__half2*)((__half*)Cout + mrow*N + col) = __floats2half2_rn(v0, v1);
                } else {
                    float2 o; o.x = v0; o.y = v1;
                    *(float2*)((float*)Cout + mrow*N + col) = o;
                }
            }
        }
    }
}

// ---------------- merged branches ----------------
#define NB_A (4*BDIM*40)   // 5120
#define NB_G (BDIM*TDIM)   // 2048
#define NB_T (BDIM*VDIM)   // 1600

__device__ __forceinline__ void attn_body(int wb, char* su) {
    int tid = threadIdx.x;
    int mode = wb / (BDIM*40);
    int rem  = wb % (BDIM*40);
    int bb = rem / 40;
    int wwin = rem % 40;
    int i0 = wwin / 5, i1 = wwin % 5;

    int*    toks = (int*)su;
    float*  sc   = (float*)(su + 320);
    float (*kv)[8][8] = (float(*)[8][8])(su + 960);
    float (*O)[33]    = (float(*)[33])(su + 1984);
    float*  pkv = (float*)(su + 1984);
    __half2 (*Xh)[52] = (__half2(*)[52])(su + 12544);

    if (tid < 80) {
        int a = tid / 10, e = tid % 10;
        int t, v;
        if      (mode == 0) { t = i0*8 + a; v = i1*10 + e; }
        else if (mode == 1) { t = i0*8 + a; v = e*5 + i1;  }
        else if (mode == 2) { t = a*8 + i0; v = i1*10 + e; }
        else                { t = a*8 + i0; v = e*5 + i1;  }
        toks[tid] = (bb*TDIM + t)*VDIM + v;
    }
    __syncthreads();

    int cbh = 128 + mode*96;
    for (int i = tid; i < 80*12; i += 256) {
        int n = i / 12, c = i - n*12;
        uint4 val = *(const uint4*)(h_f + (size_t)toks[n]*C2 + cbh + c*8);
        *(uint4*)&Xh[n][c*4] = val;
    }
    __syncthreads();

    if (tid < 80) {
        float sq = 0.f;
        #pragma unroll 8
        for (int c = 0; c < 48; c++) {
            float2 f = __half22float2(Xh[tid][c]);
            sq += f.x*f.x + f.y*f.y;
        }
        float nrm = fmaxf(sqrtf(sq), 1e-10f);
        float s = tanhf(nrm) / nrm;
        sc[tid] = s;
        float s2 = s*s;
        #pragma unroll
        for (int c = 16; c < 32; c++) {
            float2 f = __half22float2(Xh[tid][c]);
            Xh[tid][c] = __floats2half2_rn(f.x*s2, f.y*s2);
        }
    }
    __syncthreads();

    {
        int slice = tid >> 5;
        int item  = tid & 31;
        int h = item >> 3, d = item & 7;
        int nn0 = slice * 10;
        float acc[8];
        #pragma unroll
        for (int e = 0; e < 8; e++) acc[e] = 0.f;
        #pragma unroll
        for (int n = nn0; n < nn0 + 10; n++) {
            float kd = __half2float(((const __half*)Xh[n])[32 + h*8 + d]);
            float4 vv = *(const float4*)&Xh[n][32 + h*4];
            const __half2* vp = (const __half2*)&vv;
            #pragma unroll
            for (int e2 = 0; e2 < 4; e2++) {
                float2 f = __half22float2(vp[e2]);
                acc[2*e2]   += kd * f.x;
                acc[2*e2+1] += kd * f.y;
            }
        }
        #pragma unroll
        for (int e = 0; e < 8; e++)
            pkv[(e*8 + slice)*32 + item] = acc[e];
    }
    __syncthreads();

    {
        int e = tid >> 5, item = tid & 31;
        int h = item >> 3, d = item & 7;
        float s = 0.f;
        #pragma unroll
        for (int sl = 0; sl < 8; sl++) s += pkv[(e*8 + sl)*32 + item];
        kv[h][d][e] = s;
    }
    __syncthreads();

    if (tid < 32) {
        int h = tid >> 3, d = tid & 7;
        float mx = -1e30f;
        #pragma unroll
        for (int e = 0; e < 8; e++) mx = fmaxf(mx, kv[h][d][e]);
        float s = 0.f;
        #pragma unroll
        for (int e = 0; e < 8; e++) { float q = expf(kv[h][d][e] - mx); s += q; kv[h][d][e] = q; }
        float inv = 1.0f / s;
        #pragma unroll
        for (int e = 0; e < 8; e++) kv[h][d][e] *= inv;
    }
    __syncthreads();

    for (int i = tid; i < 80*16; i += 256) {
        int n = i >> 4, om = i & 15;
        int h = om >> 2, mm2 = om & 3;
        float4 qv = *(const float4*)&Xh[n][h*4];
        const __half2* qp = (const __half2*)&qv;
        float q[8];
        #pragma unroll
        for (int e2 = 0; e2 < 4; e2++) {
            float2 f = __half22float2(qp[e2]);
            q[2*e2] = f.x; q[2*e2+1] = f.y;
        }
        float4 k0 = *(const float4*)&kv[h][2*mm2][0];
        float4 k1 = *(const float4*)&kv[h][2*mm2][4];
        float4 k2 = *(const float4*)&kv[h][2*mm2+1][0];
        float4 k3 = *(const float4*)&kv[h][2*mm2+1][4];
        float a0 = q[0]*k0.x + q[1]*k0.y + q[2]*k0.z + q[3]*k0.w
                 + q[4]*k1.x + q[5]*k1.y + q[6]*k1.z + q[7]*k1.w;
        float a1 = q[0]*k2.x + q[1]*k2.y + q[2]*k2.z + q[3]*k2.w
                 + q[4]*k3.x + q[5]*k3.y + q[6]*k3.z + q[7]*k3.w;
        float s = 0.5f * sc[n];
        O[n][h*8 + 2*mm2]     = s * a0;
        O[n][h*8 + 2*mm2 + 1] = s * a1;
    }
    __syncthreads();

    if (tid < 80) {
        float sq = 0.f;
        #pragma unroll
        for (int c = 0; c < 32; c++) { float q = O[tid][c]; sq += q*q; }
        float nrm = fminf(fmaxf(sqrtf(sq), 1e-10f), 1.0f - 1e-5f);
        float s = atanhf(-nrm) / nrm;
        __half2 pk[16];
        #pragma unroll
        for (int c = 0; c < 16; c++)
            pk[c] = __floats2half2_rn(O[tid][2*c] * s, O[tid][2*c+1] * s);
        uint4* dst = (uint4*)(h_cat + (size_t)toks[tid]*CDIM + 128 + mode*32);
        const uint4* src = (const uint4*)pk;
        #pragma unroll
        for (int c = 0; c < 4; c++) dst[c] = src[c];
    }
}

__device__ __forceinline__ void gconv_body(int bt, const float* __restrict__ gw, char* su) {
    __half2 (*fg)[36] = (__half2(*)[36])su;
    int tid = threadIdx.x;
    size_t tok0 = (size_t)bt * VDIM;
    for (int i = tid; i < VDIM*8; i += 256) {
        int u = i >> 3, q = i & 7;
        *(uint4*)&fg[u][q*4] = *(const uint4*)(h_f + (tok0+u)*C2 + q*8);
    }
    __syncthreads();
    for (int i = tid; i < VDIM*8; i += 256) {
        int v = i >> 3, g = i & 7;
        const float* gwp = gw + ((size_t)g*VDIM + v)*VDIM;
        float acc[8];
        #pragma unroll
        for (int o = 0; o < 8; o++) acc[o] = 0.f;
        #pragma unroll 5
        for (int u2 = 0; u2 < VDIM/2; u2++) {
            float2 wv = *(const float2*)&gwp[u2*2];
            uint4 ra = *(const uint4*)&fg[2*u2][g*4];
            uint4 rb = *(const uint4*)&fg[2*u2+1][g*4];
            const __half2* pa = (const __half2*)&ra;
            const __half2* pb = (const __half2*)&rb;
            #pragma unroll
            for (int p = 0; p < 4; p++) {
                float2 fa = __half22float2(pa[p]);
                float2 fb = __half22float2(pb[p]);
                acc[2*p]   += wv.x*fa.x + wv.y*fb.x;
                acc[2*p+1] += wv.x*fa.y + wv.y*fb.y;
            }
        }
        __half2 pk[4];
        #pragma unroll
        for (int o = 0; o < 4; o++)
            pk[o] = __floats2half2_rn(acc[2*o], acc[2*o+1]);
        *(uint4*)(h_cat + (tok0+v)*CDIM + g*8) = *(const uint4*)pk;
    }
}

__device__ __forceinline__ void tconv_body(int blk, const float* __restrict__ w,
                                           const float* __restrict__ bias, char* su) {
    int bb = blk / VDIM, v = blk % VDIM;
    __half2 (*X)[36] = (__half2(*)[36])su;
    float* ws = (float*)(su + 9216);
    int tid = threadIdx.x;
    for (int i = tid; i < 64*56; i += 256) {
        int o = i / 56, rr = i % 56;
        ws[rr*64 + o] = w[i];
    }
    for (int i = tid; i < TDIM*8; i += 256) {
        int t = i >> 3, q = i & 7;
        *(uint4*)&X[t][q*4] =
            *(const uint4*)(h_f + ((size_t)(bb*TDIM + t)*VDIM + v)*C2 + 64 + q*8);
    }
    __syncthreads();
    int t = tid & 63, og = tid >> 6;
    size_t tokbase = ((size_t)(bb*TDIM + t)*VDIM + v)*CDIM + 64;
    #pragma unroll
    for (int hg = 0; hg < 2; hg++) {
        int g = og*2 + hg;
        float acc8[8];
        #pragma unroll
        for (int k = 0; k < 8; k++) acc8[k] = bias[g*8 + k];
        #pragma unroll
        for (int dt = 0; dt < 7; dt++) {
            int tt = t + dt - 3;
            if (tt < 0 || tt >= TDIM) continue;
            uint4 raw = *(const uint4*)&X[tt][g*4];
            const __half2* hp = (const __half2*)&raw;
            float xv[8];
            #pragma unroll
            for (int p = 0; p < 4; p++) {
                float2 f = __half22float2(hp[p]);
                xv[2*p] = f.x; xv[2*p+1] = f.y;
            }
            #pragma unroll
            for (int ic = 0; ic < 8; ic++) {
                const float* wr = &ws[(ic*7 + dt)*64 + g*8];
                #pragma unroll
                for (int k = 0; k < 8; k++) acc8[k] += xv[ic] * wr[k];
            }
        }
        __half2 pk[4];
        #pragma unroll
        for (int k = 0; k < 4; k++)
            pk[k] = __floats2half2_rn(acc8[2*k], acc8[2*k+1]);
        *(uint4*)(h_cat + tokbase + g*8) = *(const uint4*)pk;
    }
}

__global__ __launch_bounds__(256) void k_branches(const float* __restrict__ gw,
                                                  const float* __restrict__ tw,
                                                  const float* __restrict__ tb) {
    __shared__ __align__(16) char su[31232];
    int bid = blockIdx.x;
    if (bid < NB_A)            attn_body(bid, su);
    else if (bid < NB_A+NB_G)  gconv_body(bid - NB_A, gw, su);
    else                       tconv_body(bid - NB_A - NB_G, tw, tb, su);
}

// ---------------- launch ----------------
extern "C" void kernel_launch(void* const* d_in, const int* in_sizes, int n_in,
                              void* d_out, int out_size) {
    const float* x       = (const float*)d_in[0];
    const float* n1w     = (const float*)d_in[1];
    const float* n1b     = (const float*)d_in[2];
    const float* map_w   = (const float*)d_in[3];
    const float* map_b   = (const float*)d_in[4];
    const float* gconv   = (const float*)d_in[5];
    const float* tconv_w = (const float*)d_in[6];
    const float* tconv_b = (const float*)d_in[7];
    const float* proj_w  = (const float*)d_in[8];
    const float* proj_b  = (const float*)d_in[9];
    const float* n2w     = (const float*)d_in[10];
    const float* n2b     = (const float*)d_in[11];
    const float* mlp_w1  = (const float*)d_in[12];
    const float* mlp_b1  = (const float*)d_in[13];
    const float* mlp_w2  = (const float*)d_in[14];
    const float* mlp_b2  = (const float*)d_in[15];
    float* out = (float*)d_out;

    float *p_out1;
    __half *p_f, *p_xln, *p_cat, *p_ln2, *p_h;
    __half2 *p_wmap, *p_wproj, *p_wm1, *p_wm2;
    cudaGetSymbolAddress((void**)&p_out1, g_out1);
    cudaGetSymbolAddress((void**)&p_f,    h_f);
    cudaGetSymbolAddress((void**)&p_xln,  h_xln);
    cudaGetSymbolAddress((void**)&p_cat,  h_cat);
    cudaGetSymbolAddress((void**)&p_ln2,  h_ln2);
    cudaGetSymbolAddress((void**)&p_h,    h_h);
    cudaGetSymbolAddress((void**)&p_wmap,  w_map);
    cudaGetSymbolAddress((void**)&p_wproj, w_proj);
    cudaGetSymbolAddress((void**)&p_wm1,   w_m1);
    cudaGetSymbolAddress((void**)&p_wm2,   w_m2);

    int wtotal = WS1 + WS2 + WS3 + WS4;
    k_wall<<<(wtotal + 255)/256, 256>>>(map_w, p_wmap, proj_w, p_wproj,
                                        mlp_w1, p_wm1, mlp_w2, p_wm2);
    k_transln<<<BDIM*TDIM, 256>>>(x, n1w, n1b);
    k_gemm_h<3><<<dim3(C2/128, TOK/128), 256>>>(p_xln, p_wmap, map_b, nullptr, p_f, TOK, C2, CDIM);
    k_branches<<<NB_A + NB_G + NB_T, 256>>>(gconv, tconv_w, tconv_b);
    k_gemm_h<5><<<dim3(CDIM/128, TOK/128), 256>>>(p_cat, p_wproj, proj_b, x, p_out1, TOK, CDIM, CDIM);
    k_ln<<<TOK/8, 256>>>(p_out1, p_ln2, n2w, n2b);
    k_gemm_h<2><<<dim3(C4/128, TOK/128), 256>>>(p_ln2, p_wm1, mlp_b1, nullptr, p_h, TOK, C4, CDIM);
    k_gemm_h<4><<<dim3(CDIM/128, TOK/128), 256>>>(p_h, p_wm2, mlp_b2, p_out1, out, TOK, CDIM, C4);
}